// round 14
// baseline (speedup 1.0000x reference)
#include <cuda_runtime.h>
#include <cstdint>

// Delta modulation encoder: 512 independent serial scans of length 131072.
// Bit-exact fp32 replication of:
//   err = fl(x_t - r); p = err>0.1; n = err<-0.1; spike = p-n; r = fl(r + spike*0.1)
//
// R13 lesson: self-IO in the compute stream regressed; R9/R11 shape is right.
// Chain floor ~21-22 cyc/step confirmed across 3 formulations; clock saturated.
// R14 harvests overhead: TILE 256 (halves barrier/loop cost) and 4 distributed
// I/O warps (one per SMSP; warp 4+k services row k) so no single compute SMSP
// carries all LSU issue and straggles the barriers.
// dm_step: R11 10-op select form (bit-exact, measured best).

constexpr int T_LEN = 131072;
constexpr int NSEQ  = 512;            // 64 * 8
constexpr int SEQ_B = 4;              // sequences (rows) per block
constexpr int TILE  = 256;            // time steps per tile
constexpr int NT    = T_LEN / TILE;   // 512 tiles
constexpr int ROWF  = TILE + 4;       // 260 floats = 1040B stride
constexpr int NBUF  = 3;              // input ring: t, t+1 resident, t+2 in flight
constexpr int GRP   = TILE / 4;       // 64 float4 groups per tile
constexpr int NTHREADS = 256;         // 4 compute warps + 4 I/O warps

struct DMCarry {
    float rr;               // resolved recon
    float cu, cd;           // fl(rr+0.1f), fl(rr-0.1f)
    float Eu, Ed, Ez;       // x_{t+1} - {cu, cd, rr}
};

// One element. e = err_t (input), xnn = x[t+2]. Returns err_{t+1}. Bit-exact.
__device__ __forceinline__ float dm_step(float e, DMCarry& s, float xnn) {
    float eo;
    asm("{\n\t"
        ".reg .pred p, n;\n\t"
        ".reg .f32 t1, t2;\n\t"
        "setp.gt.f32 p, %7, 0f3DCCCCCD;\n\t"     // err >  0.1f
        "setp.lt.f32 n, %7, 0fBDCCCCCD;\n\t"     // err < -0.1f
        "selp.f32 t1, %4, %5, n;\n\t"            // n ? Ed : Ez
        "selp.f32 %0, %3, t1, p;\n\t"            // err' = p ? Eu : t1   (chain)
        "selp.f32 t2, %2, %1, n;\n\t"            // n ? cd : rr
        "selp.f32 %1, %6, t2, p;\n\t"            // rr' = p ? cu : t2  (reads old cu)
        "add.f32 %6, %1, 0f3DCCCCCD;\n\t"        // cu' = fl(rr' + 0.1f)
        "add.f32 %2, %1, 0fBDCCCCCD;\n\t"        // cd' = fl(rr' - 0.1f)
        "sub.f32 %3, %8, %6;\n\t"                // Eu' = fl(xnn - cu')
        "sub.f32 %4, %8, %2;\n\t"                // Ed'
        "sub.f32 %5, %8, %1;\n\t"                // Ez'
        "}"
        : "=f"(eo), "+f"(s.rr), "+f"(s.cd),
          "+f"(s.Eu), "+f"(s.Ed), "+f"(s.Ez), "+f"(s.cu)
        : "f"(e), "f"(xnn));
    return eo;
}

__device__ __forceinline__ void cp_async16(uint32_t dst_smem, const void* src) {
    asm volatile("cp.async.cg.shared.global [%0], [%1], 16;"
                 :: "r"(dst_smem), "l"(src));
}
__device__ __forceinline__ void cp_commit() {
    asm volatile("cp.async.commit_group;" ::: "memory");
}
__device__ __forceinline__ void cp_wait1() {
    asm volatile("cp.async.wait_group 1;" ::: "memory");
}
__device__ __forceinline__ void bar1() {
    asm volatile("bar.sync 1, %0;" :: "n"(NTHREADS) : "memory");
}
__device__ __forceinline__ void bar2() {
    asm volatile("bar.sync 2, %0;" :: "n"(NTHREADS) : "memory");
}

__global__ __launch_bounds__(NTHREADS, 1)
void DeltaModulationEncoder_kernel(const float* __restrict__ x,
                                   float* __restrict__ out) {
    __shared__ __align__(16) float sin_buf[NBUF][SEQ_B * ROWF];  // ~12.5 KB
    __shared__ __align__(16) float serr[2][SEQ_B * ROWF];        // ~8.3 KB

    const int tid  = threadIdx.x;
    const int warp = tid >> 5;
    const int lane = tid & 31;
    const int seqbase = blockIdx.x * SEQ_B;

    if (warp >= 4) {
        // ──────────────── I/O warp for row i = warp-4 (on SMSP i) ────────────────
        const int row = warp - 4;
        const int seq = seqbase + row;
        // Each tile row = 1024B = 2 chunks of 512B; lane covers 16B per chunk.
        const char* gsrc = (const char*)(x + (size_t)seq * T_LEN) + lane * 16;
        char*       gdst = (char*)(out + (size_t)seq * T_LEN) + lane * 16;

        uint32_t sin_addr[NBUF];
#pragma unroll
        for (int b = 0; b < NBUF; b++)
            sin_addr[b] = (uint32_t)__cvta_generic_to_shared(&sin_buf[b][0])
                        + (uint32_t)(row * ROWF * 4 + lane * 16);

        auto issue_tile = [&](int t, int slot) {
            const char* g = gsrc + (size_t)t * TILE * 4;
            const uint32_t s = sin_addr[slot];
            cp_async16(s, g);
            cp_async16(s + 512u, g + 512);
        };

        // Convert err tile -> spikes (exact: +-1.0f / +0.0f), STG directly.
        auto flush_tile = [&](int tp) {
            const float* sb = &serr[tp & 1][0] + row * ROWF + lane * 4;
            char* g = gdst + (size_t)tp * TILE * 4;
#pragma unroll
            for (int c = 0; c < 2; c++) {
                float4 e = *(const float4*)(sb + c * 128);
                float4 sp;
                sp.x = (e.x > 0.1f) ? 1.0f : ((e.x < -0.1f) ? -1.0f : 0.0f);
                sp.y = (e.y > 0.1f) ? 1.0f : ((e.y < -0.1f) ? -1.0f : 0.0f);
                sp.z = (e.z > 0.1f) ? 1.0f : ((e.z < -0.1f) ? -1.0f : 0.0f);
                sp.w = (e.w > 0.1f) ? 1.0f : ((e.w < -0.1f) ? -1.0f : 0.0f);
                *(float4*)(g + c * 512) = sp;
            }
        };

        issue_tile(0, 0); cp_commit();
        issue_tile(1, 1); cp_commit();

        int slot_w = 2;
        for (int t = 0; t < NT; ++t) {
            if (t + 2 < NT) issue_tile(t + 2, slot_w);
            cp_commit();
            cp_wait1();                 // tiles t, t+1 resident (this warp's rows)
            bar1();                     // all rows resident; release compute

            if (t > 0) flush_tile(t - 1);

            bar2();                     // serr[(t-1)&1] reusable; tile t errs visible
            slot_w = (slot_w + 1 == NBUF) ? 0 : slot_w + 1;
        }
        flush_tile(NT - 1);
    } else {
        // ──────────────────── compute warps 0-3, 1 seq each ────────────────────
        const int row = warp;
        const bool writer = (lane == 0);

        DMCarry st;
        float e;
        int s0 = 0;
        for (int t = 0; t < NT; ++t) {
            const int s1 = (s0 + 1 == NBUF) ? 0 : s0 + 1;
            bar1();                     // tiles t (slot s0), t+1 (slot s1) resident

            if (t == 0) {               // recon r0 = 0
                const float x0 = sin_buf[0][row * ROWF + 0];
                const float x1 = sin_buf[0][row * ROWF + 1];
                e      = x0;            // err_0 = fl(x0 - 0)
                st.rr  = 0.0f;
                st.cu  = 0.1f;          // fl(0 + 0.1f)
                st.cd  = -0.1f;         // fl(0 - 0.1f)
                st.Eu  = x1 - 0.1f;
                st.Ed  = x1 + 0.1f;
                st.Ez  = x1;
            }

            const float4* bk  = (const float4*)(&sin_buf[s0][0] + row * ROWF);
            const float4* bk1 = (const float4*)(&sin_buf[s1][0] + row * ROWF);
            float4* so = (float4*)(&serr[t & 1][0] + row * ROWF);

            float4 cur = bk[0];
            float4 nxt = bk[1];
#pragma unroll
            for (int g = 0; g < GRP; ++g) {
                // group g+2 (peeks into tile t+1 for g >= GRP-2; past the last
                // tile this is stale smem feeding only never-output candidates)
                const float4 nn = (g < GRP - 2) ? bk[g + 2] : bk1[g - (GRP - 2)];

                float4 ev;                       // err_t values (outputs)
                ev.x = e; e = dm_step(e, st, cur.z);
                ev.y = e; e = dm_step(e, st, cur.w);
                ev.z = e; e = dm_step(e, st, nxt.x);
                ev.w = e; e = dm_step(e, st, nxt.y);
                if (writer) so[g] = ev;          // predicated STS.128, lane 0

                cur = nxt;
                nxt = nn;
            }
            bar2();                     // hand serr[t&1] to the I/O warps
            s0 = s1;
        }
    }
}

extern "C" void kernel_launch(void* const* d_in, const int* in_sizes, int n_in,
                              void* d_out, int out_size) {
    (void)in_sizes; (void)n_in; (void)out_size;
    const float* x = (const float*)d_in[0];
    float* out     = (float*)d_out;

    // 128 blocks x (4 compute warps + 4 distributed I/O warps).
    DeltaModulationEncoder_kernel<<<NSEQ / SEQ_B, NTHREADS>>>(x, out);
}